// round 12
// baseline (speedup 1.0000x reference)
#include <cuda_runtime.h>
#include <cuda_bf16.h>
#include <cuda_fp16.h>
#include <math.h>
#include <stdint.h>

#define N_NODES   100000
#define N_EDGES   1600000
#define D         128
#define SCAN_BS   1024
#define SCAN_NB   ((N_NODES + SCAN_BS - 1) / SCAN_BS)   // 98
#define EDGE_BLKS ((N_EDGES + 255) / 256)               // 6250
#define NODE_BLKS ((N_NODES + 255) / 256)               // 391
#define WARP_BLKS ((N_NODES * 32 + 255) / 256)          // 12500
#define WPREP_BLKS 64                                   // 16384 items / 256

// ---------------------------------------------------------------------------
// Scratch (__device__ globals; referenced ONLY from device code)
// ---------------------------------------------------------------------------
__device__ __half g_x016[(size_t)N_NODES * D];  // emb[cncpt[v]] fp16 (25.6 MB)
__device__ float  g_agg [(size_t)N_NODES * D];  // agg output         (51.2 MB)
__device__ __half g_h16 [(size_t)N_NODES * D];  // layer-1 out fp16   (25.6 MB)
// Pre-split bf16 weights, packed u32 (bf16x2 along k):
// layout [mat(2)][split hi/lo(2)][f(128)][kpair(64)]
__device__ uint32_t g_Wpk[2 * 2 * 128 * 64];
__device__ int g_counts [N_NODES];
__device__ int g_rowptr [N_NODES + 1];
__device__ int g_cursor [N_NODES];
__device__ int g_sflag  [SCAN_NB];     // lookback flags: 0 = pending, total+1
__device__ int g_csrsrc [N_EDGES];

// ---------------------------------------------------------------------------
// prep: blocks [0,64) split W1/W2 into bf16 hi/lo; rest zero counts + flags
// ---------------------------------------------------------------------------
__global__ void prep_kernel(const float* __restrict__ W1,
                            const float* __restrict__ W2) {
    if (blockIdx.x < WPREP_BLKS) {
        int i = blockIdx.x * blockDim.x + threadIdx.x;   // < 16384
        int mat = i >> 13, rem = i & 8191;
        int f = rem >> 6, p = rem & 63;
        const float* W = mat ? W2 : W1;
        float w0 = __ldg(W + f * D + 2 * p);
        float w1 = __ldg(W + f * D + 2 * p + 1);
        __nv_bfloat162 hi = __floats2bfloat162_rn(w0, w1);
        float r0 = w0 - __bfloat162float(hi.x);
        float r1 = w1 - __bfloat162float(hi.y);
        __nv_bfloat162 lo = __floats2bfloat162_rn(r0, r1);
        uint32_t hiw, low;
        memcpy(&hiw, &hi, 4); memcpy(&low, &lo, 4);
        g_Wpk[((mat * 2 + 0) * 128 + f) * 64 + p] = hiw;
        g_Wpk[((mat * 2 + 1) * 128 + f) * 64 + p] = low;
    } else {
        int i = (blockIdx.x - WPREP_BLKS) * blockDim.x + threadIdx.x;
        if (i < N_NODES) g_counts[i] = 0;
        if (blockIdx.x == WPREP_BLKS && threadIdx.x < SCAN_NB)
            g_sflag[threadIdx.x] = 0;
    }
}

// ---------------------------------------------------------------------------
// hist + gather_x0 merged (independent workloads, overlap LTS vs DRAM).
// ---------------------------------------------------------------------------
__global__ void hist_gather_kernel(const int* __restrict__ dst,
                                   const int* __restrict__ cncpt,
                                   const float* __restrict__ emb) {
    if (blockIdx.x < EDGE_BLKS) {
        int e = blockIdx.x * blockDim.x + threadIdx.x;
        if (e < N_EDGES) atomicAdd(&g_counts[__ldg(dst + e)], 1);
    } else {
        int node = ((blockIdx.x - EDGE_BLKS) * blockDim.x + threadIdx.x) >> 5;
        if (node >= N_NODES) return;
        int lane = threadIdx.x & 31;
        int c = __ldg(cncpt + node);
        float4 v = __ldg(reinterpret_cast<const float4*>(emb + (size_t)c * D) + lane);
        __half2 h0 = __floats2half2_rn(v.x, v.y);
        __half2 h1 = __floats2half2_rn(v.z, v.w);
        uint2 w;
        memcpy(&w.x, &h0, 4); memcpy(&w.y, &h1, 4);
        reinterpret_cast<uint2*>(g_x016 + (size_t)node * D)[lane] = w;
    }
}

// ---------------------------------------------------------------------------
// Single-pass scan with decoupled lookback (98 blocks co-resident)
// ---------------------------------------------------------------------------
__global__ void scan_kernel() {
    __shared__ int wsum[32];
    __shared__ int s_pref;
    const int t = threadIdx.x, lane = t & 31, wid = t >> 5;
    const int j = blockIdx.x;
    int i = j * SCAN_BS + t;
    int v = (i < N_NODES) ? g_counts[i] : 0;
    int s = v;
#pragma unroll
    for (int o = 1; o < 32; o <<= 1) {
        int y = __shfl_up_sync(0xffffffffu, s, o);
        if (lane >= o) s += y;
    }
    if (lane == 31) wsum[wid] = s;
    __syncthreads();
    if (wid == 0) {
        int ws = wsum[lane];
#pragma unroll
        for (int o = 1; o < 32; o <<= 1) {
            int y = __shfl_up_sync(0xffffffffu, ws, o);
            if (lane >= o) ws += y;
        }
        wsum[lane] = ws;
    }
    __syncthreads();
    int incl = s + (wid ? wsum[wid - 1] : 0);
    if (t == SCAN_BS - 1)
        atomicExch(&g_sflag[j], incl + 1);
    if (wid == 0) {
        int p = 0;
        for (int k = lane; k < j; k += 32) {
            int f;
            do { f = atomicAdd(&g_sflag[k], 0); } while (f == 0);
            p += f - 1;
        }
#pragma unroll
        for (int o = 16; o; o >>= 1) p += __shfl_xor_sync(0xffffffffu, p, o);
        if (lane == 0) s_pref = p;
    }
    __syncthreads();
    if (i < N_NODES) {
        int rp = s_pref + incl - v;
        g_rowptr[i] = rp;
        g_cursor[i] = rp;
    }
    if (i == 0) g_rowptr[N_NODES] = N_EDGES;
}

// ---------------------------------------------------------------------------
// fill_csr: 1 edge/thread (L2 atomic-throughput bound; ILP does not help)
// ---------------------------------------------------------------------------
__global__ void fill_csr_kernel(const int* __restrict__ src,
                                const int* __restrict__ dst) {
    int e = blockIdx.x * blockDim.x + threadIdx.x;
    if (e >= N_EDGES) return;
    int d = __ldg(dst + e);
    int p = atomicAdd(&g_cursor[d], 1);
    g_csrsrc[p] = __ldg(src + e);
}

// ---------------------------------------------------------------------------
// CSR gather-aggregation over fp16 rows (256 B): warp per node, lane owns
// features 4l..4l+3 (uint2 = 4 halves); shfl-broadcast indices, 4 row loads
// in flight (1 KB/warp). fp32 accumulate.
// ---------------------------------------------------------------------------
template <bool FIRST>
__global__ void __launch_bounds__(256) agg16_kernel() {
    int node = (blockIdx.x * blockDim.x + threadIdx.x) >> 5;
    if (node >= N_NODES) return;
    int lane = threadIdx.x & 31;
    const __half* __restrict__ xin = FIRST ? g_x016 : g_h16;
    int beg = __ldg(g_rowptr + node);
    int end = __ldg(g_rowptr + node + 1);

    float4 a0 = make_float4(0.f, 0.f, 0.f, 0.f);
    float4 a1 = make_float4(0.f, 0.f, 0.f, 0.f);
    int e = beg;
    while (e < end) {
        int n = end - e; if (n > 32) n = 32;
        int idx = (lane < n) ? __ldg(g_csrsrc + e + lane) : 0;
        int j = 0;
        for (; j + 4 <= n; j += 4) {
            int s0 = __shfl_sync(0xffffffffu, idx, j);
            int s1 = __shfl_sync(0xffffffffu, idx, j + 1);
            int s2 = __shfl_sync(0xffffffffu, idx, j + 2);
            int s3 = __shfl_sync(0xffffffffu, idx, j + 3);
            uint2 r0 = __ldg(reinterpret_cast<const uint2*>(xin + (size_t)s0 * D) + lane);
            uint2 r1 = __ldg(reinterpret_cast<const uint2*>(xin + (size_t)s1 * D) + lane);
            uint2 r2 = __ldg(reinterpret_cast<const uint2*>(xin + (size_t)s2 * D) + lane);
            uint2 r3 = __ldg(reinterpret_cast<const uint2*>(xin + (size_t)s3 * D) + lane);
            float2 f;
            f = __half22float2(*reinterpret_cast<__half2*>(&r0.x)); a0.x += f.x; a0.y += f.y;
            f = __half22float2(*reinterpret_cast<__half2*>(&r0.y)); a0.z += f.x; a0.w += f.y;
            f = __half22float2(*reinterpret_cast<__half2*>(&r1.x)); a1.x += f.x; a1.y += f.y;
            f = __half22float2(*reinterpret_cast<__half2*>(&r1.y)); a1.z += f.x; a1.w += f.y;
            f = __half22float2(*reinterpret_cast<__half2*>(&r2.x)); a0.x += f.x; a0.y += f.y;
            f = __half22float2(*reinterpret_cast<__half2*>(&r2.y)); a0.z += f.x; a0.w += f.y;
            f = __half22float2(*reinterpret_cast<__half2*>(&r3.x)); a1.x += f.x; a1.y += f.y;
            f = __half22float2(*reinterpret_cast<__half2*>(&r3.y)); a1.z += f.x; a1.w += f.y;
        }
        for (; j < n; j++) {
            int s0 = __shfl_sync(0xffffffffu, idx, j);
            uint2 r0 = __ldg(reinterpret_cast<const uint2*>(xin + (size_t)s0 * D) + lane);
            float2 f;
            f = __half22float2(*reinterpret_cast<__half2*>(&r0.x)); a0.x += f.x; a0.y += f.y;
            f = __half22float2(*reinterpret_cast<__half2*>(&r0.y)); a0.z += f.x; a0.w += f.y;
        }
        e += n;
    }
    a0.x += a1.x; a0.y += a1.y; a0.z += a1.z; a0.w += a1.w;
    reinterpret_cast<float4*>(g_agg + (size_t)node * D)[lane] = a0;
}

// ---------------------------------------------------------------------------
// bf16 mma.sync helper (sm_80+ PTX; no 'a'-suffix features)
// ---------------------------------------------------------------------------
__device__ __forceinline__ void mma16816(float* c, const uint32_t* a,
                                         const uint32_t* b) {
    asm volatile(
        "mma.sync.aligned.m16n8k16.row.col.f32.bf16.bf16.f32 "
        "{%0,%1,%2,%3}, {%4,%5,%6,%7}, {%8,%9}, {%0,%1,%2,%3};"
        : "+f"(c[0]), "+f"(c[1]), "+f"(c[2]), "+f"(c[3])
        : "r"(a[0]), "r"(a[1]), "r"(a[2]), "r"(a[3]), "r"(b[0]), "r"(b[1]));
}

// ---------------------------------------------------------------------------
// Tensor-core MLP (512 threads / 16 warps — R11 ncu showed the 256-thread
// version at regs=255 (spilling) and occ=12.2%; halving per-thread state
// fixes both). Warp tile 16x64, acc[8][4]=32 regs. CTA = 128 nodes x 128 f.
//   FINAL=false: writes y=relu(agg@W^T+b) to g_h16 (fp16).
//   FINAL=true : fuses out = sigmoid(y . wout + bout).
// Error-free bf16 split: y = Xhi@Whi + Xhi@Wlo + Xlo@Whi (fp32 accum).
// ---------------------------------------------------------------------------
template <bool FINAL>
__global__ void __launch_bounds__(512) mlp_mma_kernel(const float* __restrict__ b,
                                                      const float* __restrict__ wout,
                                                      const float* __restrict__ bout,
                                                      float* __restrict__ out) {
    extern __shared__ uint32_t shw[];
    uint32_t* Xh = shw;                // [128][68]
    uint32_t* Xl = shw + 8704;
    uint32_t* Wh = shw + 2 * 8704;
    uint32_t* Wl = shw + 3 * 8704;
    __shared__ float sb[128];
    __shared__ float swout[128];
    __shared__ float nodeSum[128];

    const int t = threadIdx.x;
    const int wid = t >> 5, lane = t & 31;   // wid 0..15
    const int gbase = blockIdx.x * 128;

    // Stage W (straight copy of pre-split packed weights)
    {
        const uint32_t* srcH = g_Wpk + (FINAL ? 2 : 0) * 8192;
        const uint32_t* srcL = srcH + 8192;
#pragma unroll
        for (int i = 0; i < 16; i++) {
            int idx = t + 512 * i;            // 8192 total
            int f = idx >> 6, p = idx & 63;
            Wh[f * 68 + p] = __ldg(srcH + idx);
            Wl[f * 68 + p] = __ldg(srcL + idx);
        }
    }
    // Stage X: split g_agg rows into bf16 hi/lo (packed u32 per k-pair)
#pragma unroll
    for (int i = 0; i < 16; i++) {
        int idx = t + 512 * i;                // 8192 total
        int r = idx >> 6, p = idx & 63;
        int node = gbase + r;
        float2 v = make_float2(0.f, 0.f);
        if (node < N_NODES)
            v = *reinterpret_cast<const float2*>(g_agg + (size_t)node * D + 2 * p);
        __nv_bfloat162 hi = __floats2bfloat162_rn(v.x, v.y);
        float r0 = v.x - __bfloat162float(hi.x);
        float r1 = v.y - __bfloat162float(hi.y);
        __nv_bfloat162 lo = __floats2bfloat162_rn(r0, r1);
        uint32_t hiw, low;
        memcpy(&hiw, &hi, 4); memcpy(&low, &lo, 4);
        Xh[r * 68 + p] = hiw;
        Xl[r * 68 + p] = low;
    }
    if (t < 128) {
        sb[t] = __ldg(b + t);
        if (FINAL) { swout[t] = __ldg(wout + t); nodeSum[t] = 0.f; }
    }
    __syncthreads();

    // Warp tile: rows m0..m0+15, cols n0..n0+63 (16 warps cover 128x128)
    const int m0 = (wid >> 1) * 16, n0 = (wid & 1) * 64;
    float acc[8][4];
#pragma unroll
    for (int nt = 0; nt < 8; nt++)
#pragma unroll
        for (int j = 0; j < 4; j++) acc[nt][j] = 0.f;

    const int lq = lane >> 2, lr = lane & 3;
#pragma unroll
    for (int pass = 0; pass < 3; pass++) {
        const uint32_t* Aw = (pass < 2) ? Xh : Xl;
        const uint32_t* Bw = (pass == 1) ? Wl : Wh;
#pragma unroll
        for (int ks = 0; ks < 8; ks++) {
            const int kp = ks * 8 + lr;
            uint32_t a[4];
            a[0] = Aw[(m0 + lq) * 68 + kp];
            a[1] = Aw[(m0 + 8 + lq) * 68 + kp];
            a[2] = Aw[(m0 + lq) * 68 + kp + 4];
            a[3] = Aw[(m0 + 8 + lq) * 68 + kp + 4];
            uint32_t bf[8][2];
#pragma unroll
            for (int nt = 0; nt < 8; nt++) {
                int nr = n0 + nt * 8 + lq;
                bf[nt][0] = Bw[nr * 68 + kp];
                bf[nt][1] = Bw[nr * 68 + kp + 4];
            }
#pragma unroll
            for (int nt = 0; nt < 8; nt++)
                mma16816(acc[nt], a, bf[nt]);
        }
    }

    // Epilogue. D frag: c0,c1 -> (row m0+lq, col n0+nt*8+lr*2 +{0,1});
    //                   c2,c3 -> row m0+8+lq, same cols.
    if (!FINAL) {
        int nodeA = gbase + m0 + lq, nodeB = nodeA + 8;
#pragma unroll
        for (int nt = 0; nt < 8; nt++) {
            int c = n0 + nt * 8 + lr * 2;
            if (nodeA < N_NODES) {
                __half2 y = __floats2half2_rn(
                    fmaxf(acc[nt][0] + sb[c],     0.f),
                    fmaxf(acc[nt][1] + sb[c + 1], 0.f));
                *reinterpret_cast<__half2*>(g_h16 + (size_t)nodeA * D + c) = y;
            }
            if (nodeB < N_NODES) {
                __half2 y = __floats2half2_rn(
                    fmaxf(acc[nt][2] + sb[c],     0.f),
                    fmaxf(acc[nt][3] + sb[c + 1], 0.f));
                *reinterpret_cast<__half2*>(g_h16 + (size_t)nodeB * D + c) = y;
            }
        }
    } else {
        float pA = 0.f, pB = 0.f;
#pragma unroll
        for (int nt = 0; nt < 8; nt++) {
            int c = n0 + nt * 8 + lr * 2;
            pA += fmaxf(acc[nt][0] + sb[c],     0.f) * swout[c]
                + fmaxf(acc[nt][1] + sb[c + 1], 0.f) * swout[c + 1];
            pB += fmaxf(acc[nt][2] + sb[c],     0.f) * swout[c]
                + fmaxf(acc[nt][3] + sb[c + 1], 0.f) * swout[c + 1];
        }
        pA += __shfl_xor_sync(0xffffffffu, pA, 1);
        pA += __shfl_xor_sync(0xffffffffu, pA, 2);
        pB += __shfl_xor_sync(0xffffffffu, pB, 1);
        pB += __shfl_xor_sync(0xffffffffu, pB, 2);
        if (lr == 0) {
            atomicAdd(&nodeSum[m0 + lq], pA);
            atomicAdd(&nodeSum[m0 + 8 + lq], pB);
        }
        __syncthreads();
        if (t < 128) {
            int node = gbase + t;
            if (node < N_NODES)
                out[node] = 1.f / (1.f + expf(-(nodeSum[t] + __ldg(bout))));
        }
    }
}

// ---------------------------------------------------------------------------
extern "C" void kernel_launch(void* const* d_in, const int* in_sizes, int n_in,
                              void* d_out, int out_size) {
    const int*   cncpt = (const int*)d_in[0];
    const int*   src   = (const int*)d_in[1];
    const int*   dst   = (const int*)d_in[2];
    const float* emb   = (const float*)d_in[3];
    const float* W1    = (const float*)d_in[4];
    const float* b1    = (const float*)d_in[5];
    const float* W2    = (const float*)d_in[6];
    const float* b2    = (const float*)d_in[7];
    const float* Wout  = (const float*)d_in[8];
    const float* bout  = (const float*)d_in[9];
    float* out = (float*)d_out;

    const int MLP_SMEM = 4 * 8704 * 4;   // 139264 B
    cudaFuncSetAttribute(mlp_mma_kernel<false>, cudaFuncAttributeMaxDynamicSharedMemorySize, MLP_SMEM);
    cudaFuncSetAttribute(mlp_mma_kernel<true>,  cudaFuncAttributeMaxDynamicSharedMemorySize, MLP_SMEM);

    const int MLP_BLKS = (N_NODES + 127) / 128;   // 782

    // Prep (wsplit + zero counts/flags), CSR build overlapped with x0 gather
    prep_kernel<<<WPREP_BLKS + NODE_BLKS, 256>>>(W1, W2);
    hist_gather_kernel<<<EDGE_BLKS + WARP_BLKS, 256>>>(dst, cncpt, emb);
    scan_kernel<<<SCAN_NB, SCAN_BS>>>();
    fill_csr_kernel<<<EDGE_BLKS, 256>>>(src, dst);

    // Layer 1
    agg16_kernel<true><<<WARP_BLKS, 256>>>();
    mlp_mma_kernel<false><<<MLP_BLKS, 512, MLP_SMEM>>>(b1, nullptr, nullptr, nullptr);

    // Layer 2 (+ fused sigmoid head)
    agg16_kernel<false><<<WARP_BLKS, 256>>>();
    mlp_mma_kernel<true><<<MLP_BLKS, 512, MLP_SMEM>>>(b2, Wout, bout, out);

    (void)in_sizes; (void)n_in; (void)out_size;
}

// round 13
// speedup vs baseline: 1.0643x; 1.0643x over previous
#include <cuda_runtime.h>
#include <cuda_bf16.h>
#include <cuda_fp16.h>
#include <math.h>
#include <stdint.h>

#define N_NODES   100000
#define N_EDGES   1600000
#define D         128
#define SCAN_BS   1024
#define SCAN_NB   ((N_NODES + SCAN_BS - 1) / SCAN_BS)   // 98
#define EDGE_BLKS ((N_EDGES + 255) / 256)               // 6250
#define NODE_BLKS ((N_NODES + 255) / 256)               // 391
#define WARP_BLKS ((N_NODES * 32 + 255) / 256)          // 12500
#define WPREP_BLKS 64                                   // 16384 items / 256
#define TILE_N    64                                    // nodes per MLP CTA

// ---------------------------------------------------------------------------
// Scratch (__device__ globals; referenced ONLY from device code)
// ---------------------------------------------------------------------------
__device__ __half g_x016[(size_t)N_NODES * D];  // emb[cncpt[v]] fp16 (25.6 MB)
__device__ float  g_agg [(size_t)N_NODES * D];  // agg output         (51.2 MB)
__device__ __half g_h16 [(size_t)N_NODES * D];  // layer-1 out fp16   (25.6 MB)
// Pre-split bf16 weights, packed u32 (bf16x2 along k):
// layout [mat(2)][split hi/lo(2)][f(128)][kpair(64)]
__device__ uint32_t g_Wpk[2 * 2 * 128 * 64];
__device__ int g_counts [N_NODES];
__device__ int g_rowptr [N_NODES + 1];
__device__ int g_cursor [N_NODES];
__device__ int g_sflag  [SCAN_NB];     // lookback flags: 0 = pending, total+1
__device__ int g_csrsrc [N_EDGES];

// ---------------------------------------------------------------------------
// prep: blocks [0,64) split W1/W2 into bf16 hi/lo; rest zero counts + flags
// ---------------------------------------------------------------------------
__global__ void prep_kernel(const float* __restrict__ W1,
                            const float* __restrict__ W2) {
    if (blockIdx.x < WPREP_BLKS) {
        int i = blockIdx.x * blockDim.x + threadIdx.x;   // < 16384
        int mat = i >> 13, rem = i & 8191;
        int f = rem >> 6, p = rem & 63;
        const float* W = mat ? W2 : W1;
        float w0 = __ldg(W + f * D + 2 * p);
        float w1 = __ldg(W + f * D + 2 * p + 1);
        __nv_bfloat162 hi = __floats2bfloat162_rn(w0, w1);
        float r0 = w0 - __bfloat162float(hi.x);
        float r1 = w1 - __bfloat162float(hi.y);
        __nv_bfloat162 lo = __floats2bfloat162_rn(r0, r1);
        uint32_t hiw, low;
        memcpy(&hiw, &hi, 4); memcpy(&low, &lo, 4);
        g_Wpk[((mat * 2 + 0) * 128 + f) * 64 + p] = hiw;
        g_Wpk[((mat * 2 + 1) * 128 + f) * 64 + p] = low;
    } else {
        int i = (blockIdx.x - WPREP_BLKS) * blockDim.x + threadIdx.x;
        if (i < N_NODES) g_counts[i] = 0;
        if (blockIdx.x == WPREP_BLKS && threadIdx.x < SCAN_NB)
            g_sflag[threadIdx.x] = 0;
    }
}

// ---------------------------------------------------------------------------
// hist + gather_x0 merged (independent workloads, overlap LTS vs DRAM).
// ---------------------------------------------------------------------------
__global__ void hist_gather_kernel(const int* __restrict__ dst,
                                   const int* __restrict__ cncpt,
                                   const float* __restrict__ emb) {
    if (blockIdx.x < EDGE_BLKS) {
        int e = blockIdx.x * blockDim.x + threadIdx.x;
        if (e < N_EDGES) atomicAdd(&g_counts[__ldg(dst + e)], 1);
    } else {
        int node = ((blockIdx.x - EDGE_BLKS) * blockDim.x + threadIdx.x) >> 5;
        if (node >= N_NODES) return;
        int lane = threadIdx.x & 31;
        int c = __ldg(cncpt + node);
        float4 v = __ldg(reinterpret_cast<const float4*>(emb + (size_t)c * D) + lane);
        __half2 h0 = __floats2half2_rn(v.x, v.y);
        __half2 h1 = __floats2half2_rn(v.z, v.w);
        uint2 w;
        memcpy(&w.x, &h0, 4); memcpy(&w.y, &h1, 4);
        reinterpret_cast<uint2*>(g_x016 + (size_t)node * D)[lane] = w;
    }
}

// ---------------------------------------------------------------------------
// Single-pass scan with decoupled lookback (98 blocks co-resident)
// ---------------------------------------------------------------------------
__global__ void scan_kernel() {
    __shared__ int wsum[32];
    __shared__ int s_pref;
    const int t = threadIdx.x, lane = t & 31, wid = t >> 5;
    const int j = blockIdx.x;
    int i = j * SCAN_BS + t;
    int v = (i < N_NODES) ? g_counts[i] : 0;
    int s = v;
#pragma unroll
    for (int o = 1; o < 32; o <<= 1) {
        int y = __shfl_up_sync(0xffffffffu, s, o);
        if (lane >= o) s += y;
    }
    if (lane == 31) wsum[wid] = s;
    __syncthreads();
    if (wid == 0) {
        int ws = wsum[lane];
#pragma unroll
        for (int o = 1; o < 32; o <<= 1) {
            int y = __shfl_up_sync(0xffffffffu, ws, o);
            if (lane >= o) ws += y;
        }
        wsum[lane] = ws;
    }
    __syncthreads();
    int incl = s + (wid ? wsum[wid - 1] : 0);
    if (t == SCAN_BS - 1)
        atomicExch(&g_sflag[j], incl + 1);
    if (wid == 0) {
        int p = 0;
        for (int k = lane; k < j; k += 32) {
            int f;
            do { f = atomicAdd(&g_sflag[k], 0); } while (f == 0);
            p += f - 1;
        }
#pragma unroll
        for (int o = 16; o; o >>= 1) p += __shfl_xor_sync(0xffffffffu, p, o);
        if (lane == 0) s_pref = p;
    }
    __syncthreads();
    if (i < N_NODES) {
        int rp = s_pref + incl - v;
        g_rowptr[i] = rp;
        g_cursor[i] = rp;
    }
    if (i == 0) g_rowptr[N_NODES] = N_EDGES;
}

// ---------------------------------------------------------------------------
// fill_csr: 1 edge/thread (L2 atomic-throughput bound; ILP does not help)
// ---------------------------------------------------------------------------
__global__ void fill_csr_kernel(const int* __restrict__ src,
                                const int* __restrict__ dst) {
    int e = blockIdx.x * blockDim.x + threadIdx.x;
    if (e >= N_EDGES) return;
    int d = __ldg(dst + e);
    int p = atomicAdd(&g_cursor[d], 1);
    g_csrsrc[p] = __ldg(src + e);
}

// ---------------------------------------------------------------------------
// CSR gather-aggregation over fp16 rows (256 B): warp per node, lane owns
// features 4l..4l+3 (uint2 = 4 halves); shfl-broadcast indices, 4 row loads
// in flight (1 KB/warp). fp32 accumulate.
// ---------------------------------------------------------------------------
template <bool FIRST>
__global__ void __launch_bounds__(256) agg16_kernel() {
    int node = (blockIdx.x * blockDim.x + threadIdx.x) >> 5;
    if (node >= N_NODES) return;
    int lane = threadIdx.x & 31;
    const __half* __restrict__ xin = FIRST ? g_x016 : g_h16;
    int beg = __ldg(g_rowptr + node);
    int end = __ldg(g_rowptr + node + 1);

    float4 a0 = make_float4(0.f, 0.f, 0.f, 0.f);
    float4 a1 = make_float4(0.f, 0.f, 0.f, 0.f);
    int e = beg;
    while (e < end) {
        int n = end - e; if (n > 32) n = 32;
        int idx = (lane < n) ? __ldg(g_csrsrc + e + lane) : 0;
        int j = 0;
        for (; j + 4 <= n; j += 4) {
            int s0 = __shfl_sync(0xffffffffu, idx, j);
            int s1 = __shfl_sync(0xffffffffu, idx, j + 1);
            int s2 = __shfl_sync(0xffffffffu, idx, j + 2);
            int s3 = __shfl_sync(0xffffffffu, idx, j + 3);
            uint2 r0 = __ldg(reinterpret_cast<const uint2*>(xin + (size_t)s0 * D) + lane);
            uint2 r1 = __ldg(reinterpret_cast<const uint2*>(xin + (size_t)s1 * D) + lane);
            uint2 r2 = __ldg(reinterpret_cast<const uint2*>(xin + (size_t)s2 * D) + lane);
            uint2 r3 = __ldg(reinterpret_cast<const uint2*>(xin + (size_t)s3 * D) + lane);
            float2 f;
            f = __half22float2(*reinterpret_cast<__half2*>(&r0.x)); a0.x += f.x; a0.y += f.y;
            f = __half22float2(*reinterpret_cast<__half2*>(&r0.y)); a0.z += f.x; a0.w += f.y;
            f = __half22float2(*reinterpret_cast<__half2*>(&r1.x)); a1.x += f.x; a1.y += f.y;
            f = __half22float2(*reinterpret_cast<__half2*>(&r1.y)); a1.z += f.x; a1.w += f.y;
            f = __half22float2(*reinterpret_cast<__half2*>(&r2.x)); a0.x += f.x; a0.y += f.y;
            f = __half22float2(*reinterpret_cast<__half2*>(&r2.y)); a0.z += f.x; a0.w += f.y;
            f = __half22float2(*reinterpret_cast<__half2*>(&r3.x)); a1.x += f.x; a1.y += f.y;
            f = __half22float2(*reinterpret_cast<__half2*>(&r3.y)); a1.z += f.x; a1.w += f.y;
        }
        for (; j < n; j++) {
            int s0 = __shfl_sync(0xffffffffu, idx, j);
            uint2 r0 = __ldg(reinterpret_cast<const uint2*>(xin + (size_t)s0 * D) + lane);
            float2 f;
            f = __half22float2(*reinterpret_cast<__half2*>(&r0.x)); a0.x += f.x; a0.y += f.y;
            f = __half22float2(*reinterpret_cast<__half2*>(&r0.y)); a0.z += f.x; a0.w += f.y;
        }
        e += n;
    }
    a0.x += a1.x; a0.y += a1.y; a0.z += a1.z; a0.w += a1.w;
    reinterpret_cast<float4*>(g_agg + (size_t)node * D)[lane] = a0;
}

// ---------------------------------------------------------------------------
// bf16 mma.sync helper (sm_80+ PTX; no 'a'-suffix features)
// ---------------------------------------------------------------------------
__device__ __forceinline__ void mma16816(float* c, const uint32_t* a,
                                         const uint32_t* b) {
    asm volatile(
        "mma.sync.aligned.m16n8k16.row.col.f32.bf16.bf16.f32 "
        "{%0,%1,%2,%3}, {%4,%5,%6,%7}, {%8,%9}, {%0,%1,%2,%3};"
        : "+f"(c[0]), "+f"(c[1]), "+f"(c[2]), "+f"(c[3])
        : "r"(a[0]), "r"(a[1]), "r"(a[2]), "r"(a[3]), "r"(b[0]), "r"(b[1]));
}

// ---------------------------------------------------------------------------
// Tensor-core MLP, 64-node CTA (R7's verified GEMM geometry, standalone):
// 256 threads / 8 warps (4x2 grid), warp tile 16x64, acc[8][4]=32 regs ->
// no spills (R11 ncu: 128-node tile spilled at regs=255). Smem 104448 B ->
// 2 CTAs/SM -> 16 warps/SM, doubled memory parallelism on the agg stream.
//   FINAL=false: writes y=relu(agg@W^T+b) to g_h16 (fp16).
//   FINAL=true : fuses out = sigmoid(y . wout + bout).
// Error-free bf16 split: y = Xhi@Whi + Xhi@Wlo + Xlo@Whi (fp32 accum).
// ---------------------------------------------------------------------------
template <bool FINAL>
__global__ void __launch_bounds__(256) mlp_mma_kernel(const float* __restrict__ b,
                                                      const float* __restrict__ wout,
                                                      const float* __restrict__ bout,
                                                      float* __restrict__ out) {
    extern __shared__ uint32_t shw[];
    uint32_t* Xh = shw;                    // [64][68]
    uint32_t* Xl = shw + 4352;
    uint32_t* Wh = shw + 2 * 4352;         // [128][68]
    uint32_t* Wl = shw + 2 * 4352 + 8704;
    __shared__ float sb[128];
    __shared__ float swout[128];
    __shared__ float nodeSum[TILE_N];

    const int t = threadIdx.x;
    const int wid = t >> 5, lane = t & 31;
    const int gbase = blockIdx.x * TILE_N;

    // Stage W (straight copy of pre-split packed weights; L2-resident)
    {
        const uint32_t* srcH = g_Wpk + (FINAL ? 2 : 0) * 8192;
        const uint32_t* srcL = srcH + 8192;
#pragma unroll
        for (int i = 0; i < 32; i++) {
            int idx = t + 256 * i;            // 8192 total
            int f = idx >> 6, p = idx & 63;
            Wh[f * 68 + p] = __ldg(srcH + idx);
            Wl[f * 68 + p] = __ldg(srcL + idx);
        }
    }
    // Stage X: split g_agg rows into bf16 hi/lo (packed u32 per k-pair)
#pragma unroll
    for (int i = 0; i < 16; i++) {
        int idx = t + 256 * i;                // 4096 total
        int r = idx >> 6, p = idx & 63;
        int node = gbase + r;
        float2 v = make_float2(0.f, 0.f);
        if (node < N_NODES)
            v = *reinterpret_cast<const float2*>(g_agg + (size_t)node * D + 2 * p);
        __nv_bfloat162 hi = __floats2bfloat162_rn(v.x, v.y);
        float r0 = v.x - __bfloat162float(hi.x);
        float r1 = v.y - __bfloat162float(hi.y);
        __nv_bfloat162 lo = __floats2bfloat162_rn(r0, r1);
        uint32_t hiw, low;
        memcpy(&hiw, &hi, 4); memcpy(&low, &lo, 4);
        Xh[r * 68 + p] = hiw;
        Xl[r * 68 + p] = low;
    }
    if (t < 128) {
        sb[t] = __ldg(b + t);
        if (FINAL) swout[t] = __ldg(wout + t);
    }
    if (FINAL && t < TILE_N) nodeSum[t] = 0.f;
    __syncthreads();

    // Warp tile: rows m0..m0+15, cols n0..n0+63 (8 warps cover 64x128)
    const int m0 = (wid >> 1) * 16, n0 = (wid & 1) * 64;
    float acc[8][4];
#pragma unroll
    for (int nt = 0; nt < 8; nt++)
#pragma unroll
        for (int j = 0; j < 4; j++) acc[nt][j] = 0.f;

    const int lq = lane >> 2, lr = lane & 3;
#pragma unroll
    for (int pass = 0; pass < 3; pass++) {
        const uint32_t* Aw = (pass < 2) ? Xh : Xl;
        const uint32_t* Bw = (pass == 1) ? Wl : Wh;
#pragma unroll
        for (int ks = 0; ks < 8; ks++) {
            const int kp = ks * 8 + lr;
            uint32_t a[4];
            a[0] = Aw[(m0 + lq) * 68 + kp];
            a[1] = Aw[(m0 + 8 + lq) * 68 + kp];
            a[2] = Aw[(m0 + lq) * 68 + kp + 4];
            a[3] = Aw[(m0 + 8 + lq) * 68 + kp + 4];
            uint32_t bf[8][2];
#pragma unroll
            for (int nt = 0; nt < 8; nt++) {
                int nr = n0 + nt * 8 + lq;
                bf[nt][0] = Bw[nr * 68 + kp];
                bf[nt][1] = Bw[nr * 68 + kp + 4];
            }
#pragma unroll
            for (int nt = 0; nt < 8; nt++)
                mma16816(acc[nt], a, bf[nt]);
        }
    }

    // Epilogue. D frag: c0,c1 -> (row m0+lq, col n0+nt*8+lr*2 +{0,1});
    //                   c2,c3 -> row m0+8+lq, same cols.
    if (!FINAL) {
        int nodeA = gbase + m0 + lq, nodeB = nodeA + 8;
#pragma unroll
        for (int nt = 0; nt < 8; nt++) {
            int c = n0 + nt * 8 + lr * 2;
            if (nodeA < N_NODES) {
                __half2 y = __floats2half2_rn(
                    fmaxf(acc[nt][0] + sb[c],     0.f),
                    fmaxf(acc[nt][1] + sb[c + 1], 0.f));
                *reinterpret_cast<__half2*>(g_h16 + (size_t)nodeA * D + c) = y;
            }
            if (nodeB < N_NODES) {
                __half2 y = __floats2half2_rn(
                    fmaxf(acc[nt][2] + sb[c],     0.f),
                    fmaxf(acc[nt][3] + sb[c + 1], 0.f));
                *reinterpret_cast<__half2*>(g_h16 + (size_t)nodeB * D + c) = y;
            }
        }
    } else {
        float pA = 0.f, pB = 0.f;
#pragma unroll
        for (int nt = 0; nt < 8; nt++) {
            int c = n0 + nt * 8 + lr * 2;
            pA += fmaxf(acc[nt][0] + sb[c],     0.f) * swout[c]
                + fmaxf(acc[nt][1] + sb[c + 1], 0.f) * swout[c + 1];
            pB += fmaxf(acc[nt][2] + sb[c],     0.f) * swout[c]
                + fmaxf(acc[nt][3] + sb[c + 1], 0.f) * swout[c + 1];
        }
        pA += __shfl_xor_sync(0xffffffffu, pA, 1);
        pA += __shfl_xor_sync(0xffffffffu, pA, 2);
        pB += __shfl_xor_sync(0xffffffffu, pB, 1);
        pB += __shfl_xor_sync(0xffffffffu, pB, 2);
        if (lr == 0) {
            atomicAdd(&nodeSum[m0 + lq], pA);
            atomicAdd(&nodeSum[m0 + 8 + lq], pB);
        }
        __syncthreads();
        if (t < TILE_N) {
            int node = gbase + t;
            if (node < N_NODES)
                out[node] = 1.f / (1.f + expf(-(nodeSum[t] + __ldg(bout))));
        }
    }
}

// ---------------------------------------------------------------------------
extern "C" void kernel_launch(void* const* d_in, const int* in_sizes, int n_in,
                              void* d_out, int out_size) {
    const int*   cncpt = (const int*)d_in[0];
    const int*   src   = (const int*)d_in[1];
    const int*   dst   = (const int*)d_in[2];
    const float* emb   = (const float*)d_in[3];
    const float* W1    = (const float*)d_in[4];
    const float* b1    = (const float*)d_in[5];
    const float* W2    = (const float*)d_in[6];
    const float* b2    = (const float*)d_in[7];
    const float* Wout  = (const float*)d_in[8];
    const float* bout  = (const float*)d_in[9];
    float* out = (float*)d_out;

    const int MLP_SMEM = (2 * 4352 + 2 * 8704) * 4;   // 104448 B -> 2 CTAs/SM
    cudaFuncSetAttribute(mlp_mma_kernel<false>, cudaFuncAttributeMaxDynamicSharedMemorySize, MLP_SMEM);
    cudaFuncSetAttribute(mlp_mma_kernel<true>,  cudaFuncAttributeMaxDynamicSharedMemorySize, MLP_SMEM);

    const int MLP_BLKS = (N_NODES + TILE_N - 1) / TILE_N;   // 1563

    // Prep (wsplit + zero counts/flags), CSR build overlapped with x0 gather
    prep_kernel<<<WPREP_BLKS + NODE_BLKS, 256>>>(W1, W2);
    hist_gather_kernel<<<EDGE_BLKS + WARP_BLKS, 256>>>(dst, cncpt, emb);
    scan_kernel<<<SCAN_NB, SCAN_BS>>>();
    fill_csr_kernel<<<EDGE_BLKS, 256>>>(src, dst);

    // Layer 1
    agg16_kernel<true><<<WARP_BLKS, 256>>>();
    mlp_mma_kernel<false><<<MLP_BLKS, 256, MLP_SMEM>>>(b1, nullptr, nullptr, nullptr);

    // Layer 2 (+ fused sigmoid head)
    agg16_kernel<false><<<WARP_BLKS, 256>>>();
    mlp_mma_kernel<true><<<MLP_BLKS, 256, MLP_SMEM>>>(b2, Wout, bout, out);

    (void)in_sizes; (void)n_in; (void)out_size;
}

// round 14
// speedup vs baseline: 1.4286x; 1.3423x over previous
#include <cuda_runtime.h>
#include <cuda_bf16.h>
#include <cuda_fp16.h>
#include <math.h>
#include <stdint.h>

#define N_NODES   100000
#define N_EDGES   1600000
#define D         128
#define SCAN_BS   1024
#define SCAN_NB   ((N_NODES + SCAN_BS - 1) / SCAN_BS)   // 98
#define EDGE_BLKS ((N_EDGES + 255) / 256)               // 6250
#define NODE_BLKS ((N_NODES + 255) / 256)               // 391
#define WARP_BLKS ((N_NODES * 32 + 255) / 256)          // 12500
#define WPREP_BLKS 64                                   // 16384 items / 256

// ---------------------------------------------------------------------------
// Scratch (__device__ globals; referenced ONLY from device code)
// ---------------------------------------------------------------------------
__device__ __half g_x016 [(size_t)N_NODES * D];  // emb[cncpt[v]] fp16 (25.6 MB)
__device__ __half g_agg16[(size_t)N_NODES * D];  // agg output fp16    (25.6 MB)
__device__ __half g_h16  [(size_t)N_NODES * D];  // layer-1 out fp16   (25.6 MB)
// fp16 weights, packed u32 (fp16x2 along k): layout [mat(2)][f(128)][kpair(64)]
__device__ uint32_t g_Wpk16[2 * 128 * 64];
__device__ int g_counts [N_NODES];
__device__ int g_rowptr [N_NODES + 1];
__device__ int g_cursor [N_NODES];
__device__ int g_sflag  [SCAN_NB];     // lookback flags: 0 = pending, total+1
__device__ int g_csrsrc [N_EDGES];

// ---------------------------------------------------------------------------
// prep: blocks [0,64) convert W1/W2 to packed fp16; rest zero counts + flags
// ---------------------------------------------------------------------------
__global__ void prep_kernel(const float* __restrict__ W1,
                            const float* __restrict__ W2) {
    if (blockIdx.x < WPREP_BLKS) {
        int i = blockIdx.x * blockDim.x + threadIdx.x;   // < 16384
        int mat = i >> 13, rem = i & 8191;
        int f = rem >> 6, p = rem & 63;
        const float* W = mat ? W2 : W1;
        float w0 = __ldg(W + f * D + 2 * p);
        float w1 = __ldg(W + f * D + 2 * p + 1);
        __half2 h = __floats2half2_rn(w0, w1);
        uint32_t hw;
        memcpy(&hw, &h, 4);
        g_Wpk16[(mat * 128 + f) * 64 + p] = hw;
    } else {
        int i = (blockIdx.x - WPREP_BLKS) * blockDim.x + threadIdx.x;
        if (i < N_NODES) g_counts[i] = 0;
        if (blockIdx.x == WPREP_BLKS && threadIdx.x < SCAN_NB)
            g_sflag[threadIdx.x] = 0;
    }
}

// ---------------------------------------------------------------------------
// hist + gather_x0 merged (independent workloads, overlap LTS vs DRAM).
// ---------------------------------------------------------------------------
__global__ void hist_gather_kernel(const int* __restrict__ dst,
                                   const int* __restrict__ cncpt,
                                   const float* __restrict__ emb) {
    if (blockIdx.x < EDGE_BLKS) {
        int e = blockIdx.x * blockDim.x + threadIdx.x;
        if (e < N_EDGES) atomicAdd(&g_counts[__ldg(dst + e)], 1);
    } else {
        int node = ((blockIdx.x - EDGE_BLKS) * blockDim.x + threadIdx.x) >> 5;
        if (node >= N_NODES) return;
        int lane = threadIdx.x & 31;
        int c = __ldg(cncpt + node);
        float4 v = __ldg(reinterpret_cast<const float4*>(emb + (size_t)c * D) + lane);
        __half2 h0 = __floats2half2_rn(v.x, v.y);
        __half2 h1 = __floats2half2_rn(v.z, v.w);
        uint2 w;
        memcpy(&w.x, &h0, 4); memcpy(&w.y, &h1, 4);
        reinterpret_cast<uint2*>(g_x016 + (size_t)node * D)[lane] = w;
    }
}

// ---------------------------------------------------------------------------
// Single-pass scan with decoupled lookback (98 blocks co-resident)
// ---------------------------------------------------------------------------
__global__ void scan_kernel() {
    __shared__ int wsum[32];
    __shared__ int s_pref;
    const int t = threadIdx.x, lane = t & 31, wid = t >> 5;
    const int j = blockIdx.x;
    int i = j * SCAN_BS + t;
    int v = (i < N_NODES) ? g_counts[i] : 0;
    int s = v;
#pragma unroll
    for (int o = 1; o < 32; o <<= 1) {
        int y = __shfl_up_sync(0xffffffffu, s, o);
        if (lane >= o) s += y;
    }
    if (lane == 31) wsum[wid] = s;
    __syncthreads();
    if (wid == 0) {
        int ws = wsum[lane];
#pragma unroll
        for (int o = 1; o < 32; o <<= 1) {
            int y = __shfl_up_sync(0xffffffffu, ws, o);
            if (lane >= o) ws += y;
        }
        wsum[lane] = ws;
    }
    __syncthreads();
    int incl = s + (wid ? wsum[wid - 1] : 0);
    if (t == SCAN_BS - 1)
        atomicExch(&g_sflag[j], incl + 1);
    if (wid == 0) {
        int p = 0;
        for (int k = lane; k < j; k += 32) {
            int f;
            do { f = atomicAdd(&g_sflag[k], 0); } while (f == 0);
            p += f - 1;
        }
#pragma unroll
        for (int o = 16; o; o >>= 1) p += __shfl_xor_sync(0xffffffffu, p, o);
        if (lane == 0) s_pref = p;
    }
    __syncthreads();
    if (i < N_NODES) {
        int rp = s_pref + incl - v;
        g_rowptr[i] = rp;
        g_cursor[i] = rp;
    }
    if (i == 0) g_rowptr[N_NODES] = N_EDGES;
}

// ---------------------------------------------------------------------------
// fill_csr: 1 edge/thread (L2 atomic-throughput bound; ILP does not help)
// ---------------------------------------------------------------------------
__global__ void fill_csr_kernel(const int* __restrict__ src,
                                const int* __restrict__ dst) {
    int e = blockIdx.x * blockDim.x + threadIdx.x;
    if (e >= N_EDGES) return;
    int d = __ldg(dst + e);
    int p = atomicAdd(&g_cursor[d], 1);
    g_csrsrc[p] = __ldg(src + e);
}

// ---------------------------------------------------------------------------
// CSR gather-aggregation over fp16 rows (256 B): warp per node, lane owns
// features 4l..4l+3 (uint2 = 4 halves); shfl-broadcast indices, 4 row loads
// in flight (1 KB/warp). fp32 accumulate; fp16 output (the GEMM consumes
// fp16 anyway, so this quantization is free).
// ---------------------------------------------------------------------------
template <bool FIRST>
__global__ void __launch_bounds__(256) agg16_kernel() {
    int node = (blockIdx.x * blockDim.x + threadIdx.x) >> 5;
    if (node >= N_NODES) return;
    int lane = threadIdx.x & 31;
    const __half* __restrict__ xin = FIRST ? g_x016 : g_h16;
    int beg = __ldg(g_rowptr + node);
    int end = __ldg(g_rowptr + node + 1);

    float4 a0 = make_float4(0.f, 0.f, 0.f, 0.f);
    float4 a1 = make_float4(0.f, 0.f, 0.f, 0.f);
    int e = beg;
    while (e < end) {
        int n = end - e; if (n > 32) n = 32;
        int idx = (lane < n) ? __ldg(g_csrsrc + e + lane) : 0;
        int j = 0;
        for (; j + 4 <= n; j += 4) {
            int s0 = __shfl_sync(0xffffffffu, idx, j);
            int s1 = __shfl_sync(0xffffffffu, idx, j + 1);
            int s2 = __shfl_sync(0xffffffffu, idx, j + 2);
            int s3 = __shfl_sync(0xffffffffu, idx, j + 3);
            uint2 r0 = __ldg(reinterpret_cast<const uint2*>(xin + (size_t)s0 * D) + lane);
            uint2 r1 = __ldg(reinterpret_cast<const uint2*>(xin + (size_t)s1 * D) + lane);
            uint2 r2 = __ldg(reinterpret_cast<const uint2*>(xin + (size_t)s2 * D) + lane);
            uint2 r3 = __ldg(reinterpret_cast<const uint2*>(xin + (size_t)s3 * D) + lane);
            float2 f;
            f = __half22float2(*reinterpret_cast<__half2*>(&r0.x)); a0.x += f.x; a0.y += f.y;
            f = __half22float2(*reinterpret_cast<__half2*>(&r0.y)); a0.z += f.x; a0.w += f.y;
            f = __half22float2(*reinterpret_cast<__half2*>(&r1.x)); a1.x += f.x; a1.y += f.y;
            f = __half22float2(*reinterpret_cast<__half2*>(&r1.y)); a1.z += f.x; a1.w += f.y;
            f = __half22float2(*reinterpret_cast<__half2*>(&r2.x)); a0.x += f.x; a0.y += f.y;
            f = __half22float2(*reinterpret_cast<__half2*>(&r2.y)); a0.z += f.x; a0.w += f.y;
            f = __half22float2(*reinterpret_cast<__half2*>(&r3.x)); a1.x += f.x; a1.y += f.y;
            f = __half22float2(*reinterpret_cast<__half2*>(&r3.y)); a1.z += f.x; a1.w += f.y;
        }
        for (; j < n; j++) {
            int s0 = __shfl_sync(0xffffffffu, idx, j);
            uint2 r0 = __ldg(reinterpret_cast<const uint2*>(xin + (size_t)s0 * D) + lane);
            float2 f;
            f = __half22float2(*reinterpret_cast<__half2*>(&r0.x)); a0.x += f.x; a0.y += f.y;
            f = __half22float2(*reinterpret_cast<__half2*>(&r0.y)); a0.z += f.x; a0.w += f.y;
        }
        e += n;
    }
    a0.x += a1.x; a0.y += a1.y; a0.z += a1.z; a0.w += a1.w;
    __half2 h0 = __floats2half2_rn(a0.x, a0.y);
    __half2 h1 = __floats2half2_rn(a0.z, a0.w);
    uint2 w;
    memcpy(&w.x, &h0, 4); memcpy(&w.y, &h1, 4);
    reinterpret_cast<uint2*>(g_agg16 + (size_t)node * D)[lane] = w;
}

// ---------------------------------------------------------------------------
// fp16 mma.sync helper (sm_80+ PTX; fp32 accumulate)
// ---------------------------------------------------------------------------
__device__ __forceinline__ void mma16816(float* c, const uint32_t* a,
                                         const uint32_t* b) {
    asm volatile(
        "mma.sync.aligned.m16n8k16.row.col.f32.f16.f16.f32 "
        "{%0,%1,%2,%3}, {%4,%5,%6,%7}, {%8,%9}, {%0,%1,%2,%3};"
        : "+f"(c[0]), "+f"(c[1]), "+f"(c[2]), "+f"(c[3])
        : "r"(a[0]), "r"(a[1]), "r"(a[2]), "r"(a[3]), "r"(b[0]), "r"(b[1]));
}

// ---------------------------------------------------------------------------
// Tensor-core MLP, single-pass fp16 (replaces the 3-pass bf16 split — the
// split forced 140 KB smem + spills; fp16 e5m10 gives 4x finer mantissa than
// bf16 so one pass suffices within the error budget).
// CTA = 128 nodes x 128 features, 256 threads, warps 4x2 (32x64 tiles),
// smem = (X + W)[128][68] u32 = 69632 B -> 2 CTAs/SM. X staging = raw copy
// (agg already wrote fp16). Accumulate fp32.
//   FINAL=false: writes y=relu(agg@W^T+b) to g_h16 (fp16).
//   FINAL=true : fuses out = sigmoid(y . wout + bout).
// ---------------------------------------------------------------------------
template <bool FINAL>
__global__ void __launch_bounds__(256) mlp_mma_kernel(const float* __restrict__ b,
                                                      const float* __restrict__ wout,
                                                      const float* __restrict__ bout,
                                                      float* __restrict__ out) {
    extern __shared__ uint32_t shw[];
    uint32_t* Xs = shw;                // [128][68]
    uint32_t* Ws = shw + 8704;         // [128][68]
    __shared__ float sb[128];
    __shared__ float swout[128];
    __shared__ float nodeSum[128];

    const int t = threadIdx.x;
    const int wid = t >> 5, lane = t & 31;
    const int gbase = blockIdx.x * 128;

    // Stage W (straight copy of packed fp16 weights; L2-resident 32 KB)
    {
        const uint32_t* srcW = g_Wpk16 + (FINAL ? 8192 : 0);
#pragma unroll
        for (int i = 0; i < 32; i++) {
            int idx = t + 256 * i;            // 8192 total
            int f = idx >> 6, p = idx & 63;
            Ws[f * 68 + p] = __ldg(srcW + idx);
        }
    }
    // Stage X: raw uint4 copy of fp16 agg rows (16 uint4 per 256-B row)
#pragma unroll
    for (int i = 0; i < 8; i++) {
        int idx = t + 256 * i;                // 2048 total
        int r = idx >> 4, q = idx & 15;
        int node = gbase + r;
        uint4 v = make_uint4(0u, 0u, 0u, 0u);
        if (node < N_NODES)
            v = *(reinterpret_cast<const uint4*>(g_agg16 + (size_t)node * D) + q);
        *reinterpret_cast<uint4*>(Xs + r * 68 + 4 * q) = v;
    }
    if (t < 128) {
        sb[t] = __ldg(b + t);
        if (FINAL) { swout[t] = __ldg(wout + t); nodeSum[t] = 0.f; }
    }
    __syncthreads();

    // Warp tile: rows m0..m0+31, cols n0..n0+63
    const int m0 = (wid >> 1) * 32, n0 = (wid & 1) * 64;
    float acc[2][8][4];
#pragma unroll
    for (int mt = 0; mt < 2; mt++)
#pragma unroll
        for (int nt = 0; nt < 8; nt++)
#pragma unroll
            for (int j = 0; j < 4; j++) acc[mt][nt][j] = 0.f;

    const int lq = lane >> 2, lr = lane & 3;
#pragma unroll
    for (int ks = 0; ks < 8; ks++) {
        const int kp = ks * 8 + lr;
        uint32_t a[2][4];
#pragma unroll
        for (int mt = 0; mt < 2; mt++) {
            int r0i = m0 + mt * 16 + lq;
            a[mt][0] = Xs[r0i * 68 + kp];
            a[mt][1] = Xs[(r0i + 8) * 68 + kp];
            a[mt][2] = Xs[r0i * 68 + kp + 4];
            a[mt][3] = Xs[(r0i + 8) * 68 + kp + 4];
        }
        uint32_t bf[8][2];
#pragma unroll
        for (int nt = 0; nt < 8; nt++) {
            int nr = n0 + nt * 8 + lq;
            bf[nt][0] = Ws[nr * 68 + kp];
            bf[nt][1] = Ws[nr * 68 + kp + 4];
        }
#pragma unroll
        for (int mt = 0; mt < 2; mt++)
#pragma unroll
            for (int nt = 0; nt < 8; nt++)
                mma16816(acc[mt][nt], a[mt], bf[nt]);
    }

    // Epilogue. D frag: c0,c1 -> (row m0+mt*16+lq, col n0+nt*8+lr*2 +{0,1});
    //                   c2,c3 -> row+8, same cols.
    if (!FINAL) {
#pragma unroll
        for (int mt = 0; mt < 2; mt++) {
            int rA = m0 + mt * 16 + lq;
            int nodeA = gbase + rA, nodeB = nodeA + 8;
#pragma unroll
            for (int nt = 0; nt < 8; nt++) {
                int c = n0 + nt * 8 + lr * 2;
                if (nodeA < N_NODES) {
                    __half2 y = __floats2half2_rn(
                        fmaxf(acc[mt][nt][0] + sb[c],     0.f),
                        fmaxf(acc[mt][nt][1] + sb[c + 1], 0.f));
                    *reinterpret_cast<__half2*>(g_h16 + (size_t)nodeA * D + c) = y;
                }
                if (nodeB < N_NODES) {
                    __half2 y = __floats2half2_rn(
                        fmaxf(acc[mt][nt][2] + sb[c],     0.f),
                        fmaxf(acc[mt][nt][3] + sb[c + 1], 0.f));
                    *reinterpret_cast<__half2*>(g_h16 + (size_t)nodeB * D + c) = y;
                }
            }
        }
    } else {
#pragma unroll
        for (int mt = 0; mt < 2; mt++) {
            float pA = 0.f, pB = 0.f;
            int rA = m0 + mt * 16 + lq;
#pragma unroll
            for (int nt = 0; nt < 8; nt++) {
                int c = n0 + nt * 8 + lr * 2;
                pA += fmaxf(acc[mt][nt][0] + sb[c],     0.f) * swout[c]
                    + fmaxf(acc[mt][nt][1] + sb[c + 1], 0.f) * swout[c + 1];
                pB += fmaxf(acc[mt][nt][2] + sb[c],     0.f) * swout[c]
                    + fmaxf(acc[mt][nt][3] + sb[c + 1], 0.f) * swout[c + 1];
            }
            pA += __shfl_xor_sync(0xffffffffu, pA, 1);
            pA += __shfl_xor_sync(0xffffffffu, pA, 2);
            pB += __shfl_xor_sync(0xffffffffu, pB, 1);
            pB += __shfl_xor_sync(0xffffffffu, pB, 2);
            if (lr == 0) {
                atomicAdd(&nodeSum[rA], pA);
                atomicAdd(&nodeSum[rA + 8], pB);
            }
        }
        __syncthreads();
        if (t < 128) {
            int node = gbase + t;
            if (node < N_NODES)
                out[node] = 1.f / (1.f + expf(-(nodeSum[t] + __ldg(bout))));
        }
    }
}

// ---------------------------------------------------------------------------
extern "C" void kernel_launch(void* const* d_in, const int* in_sizes, int n_in,
                              void* d_out, int out_size) {
    const int*   cncpt = (const int*)d_in[0];
    const int*   src   = (const int*)d_in[1];
    const int*   dst   = (const int*)d_in[2];
    const float* emb   = (const float*)d_in[3];
    const float* W1    = (const float*)d_in[4];
    const float* b1    = (const float*)d_in[5];
    const float* W2    = (const float*)d_in[6];
    const float* b2    = (const float*)d_in[7];
    const float* Wout  = (const float*)d_in[8];
    const float* bout  = (const float*)d_in[9];
    float* out = (float*)d_out;

    const int MLP_SMEM = 2 * 8704 * 4;   // 69632 B -> 2 CTAs/SM
    cudaFuncSetAttribute(mlp_mma_kernel<false>, cudaFuncAttributeMaxDynamicSharedMemorySize, MLP_SMEM);
    cudaFuncSetAttribute(mlp_mma_kernel<true>,  cudaFuncAttributeMaxDynamicSharedMemorySize, MLP_SMEM);

    const int MLP_BLKS = (N_NODES + 127) / 128;   // 782

    // Prep (W->fp16 + zero counts/flags), CSR build overlapped with x0 gather
    prep_kernel<<<WPREP_BLKS + NODE_BLKS, 256>>>(W1, W2);
    hist_gather_kernel<<<EDGE_BLKS + WARP_BLKS, 256>>>(dst, cncpt, emb);
    scan_kernel<<<SCAN_NB, SCAN_BS>>>();
    fill_csr_kernel<<<EDGE_BLKS, 256>>>(src, dst);

    // Layer 1
    agg16_kernel<true><<<WARP_BLKS, 256>>>();
    mlp_mma_kernel<false><<<MLP_BLKS, 256, MLP_SMEM>>>(b1, nullptr, nullptr, nullptr);

    // Layer 2 (+ fused sigmoid head)
    agg16_kernel<false><<<WARP_BLKS, 256>>>();
    mlp_mma_kernel<true><<<MLP_BLKS, 256, MLP_SMEM>>>(b2, Wout, bout, out);

    (void)in_sizes; (void)n_in; (void)out_size;
}

// round 15
// speedup vs baseline: 1.4339x; 1.0037x over previous
#include <cuda_runtime.h>
#include <cuda_bf16.h>
#include <cuda_fp16.h>
#include <math.h>
#include <stdint.h>

#define N_NODES   100000
#define N_EDGES   1600000
#define D         128
#define SCAN_BS   1024
#define SCAN_NB   ((N_NODES + SCAN_BS - 1) / SCAN_BS)   // 98
#define EDGE_BLKS ((N_EDGES + 255) / 256)               // 6250
#define WARP_BLKS ((N_NODES * 32 + 255) / 256)          // 12500
#define WPREP_BLKS 64                                   // 16384 items / 256

// ---------------------------------------------------------------------------
// Scratch (__device__ globals; referenced ONLY from device code).
// Self-cleaning: g_counts is zeroed inside scan right after being read
// (globals start zeroed -> call 1 covered; every call leaves them zero).
// g_sflag is zeroed by kernel 1 of every call (before scan runs).
// ---------------------------------------------------------------------------
__device__ __half g_x016 [(size_t)N_NODES * D];  // emb[cncpt[v]] fp16 (25.6 MB)
__device__ __half g_agg16[(size_t)N_NODES * D];  // agg output fp16    (25.6 MB)
__device__ __half g_h16  [(size_t)N_NODES * D];  // layer-1 out fp16   (25.6 MB)
// fp16 weights, packed u32 (fp16x2 along k): layout [mat(2)][f(128)][kpair(64)]
__device__ uint32_t g_Wpk16[2 * 128 * 64];
__device__ int g_counts [N_NODES];
__device__ int g_rowptr [N_NODES + 1];
__device__ int g_rank   [N_EDGES];     // edge's rank within its dst bucket
__device__ int g_sflag  [SCAN_NB];     // lookback flags: 0 = pending, total+1
__device__ int g_csrsrc [N_EDGES];

// ---------------------------------------------------------------------------
// Kernel 1: W->fp16 convert + histogram(with rank capture) + x0 gather,
// all independent workloads in one launch.
//   blocks [0, WPREP_BLKS):          W convert (block 0 also zeros sflag)
//   blocks [WPREP_BLKS, +EDGE_BLKS): rank[e] = atomicAdd(&counts[dst[e]], 1)
//   remaining WARP_BLKS blocks:      g_x016[v] = fp16(emb[cncpt[v]])
// counts are zero on entry (self-cleaned by the previous call's scan).
// ---------------------------------------------------------------------------
__global__ void prep_hist_gather_kernel(const float* __restrict__ W1,
                                        const float* __restrict__ W2,
                                        const int* __restrict__ dst,
                                        const int* __restrict__ cncpt,
                                        const float* __restrict__ emb) {
    if (blockIdx.x < WPREP_BLKS) {
        if (blockIdx.x == 0 && threadIdx.x < SCAN_NB)
            g_sflag[threadIdx.x] = 0;
        int i = blockIdx.x * blockDim.x + threadIdx.x;   // < 16384
        int mat = i >> 13, rem = i & 8191;
        int f = rem >> 6, p = rem & 63;
        const float* W = mat ? W2 : W1;
        float w0 = __ldg(W + f * D + 2 * p);
        float w1 = __ldg(W + f * D + 2 * p + 1);
        __half2 h = __floats2half2_rn(w0, w1);
        uint32_t hw;
        memcpy(&hw, &h, 4);
        g_Wpk16[(mat * 128 + f) * 64 + p] = hw;
    } else if (blockIdx.x < WPREP_BLKS + EDGE_BLKS) {
        int e = (blockIdx.x - WPREP_BLKS) * blockDim.x + threadIdx.x;
        if (e < N_EDGES)
            g_rank[e] = atomicAdd(&g_counts[__ldg(dst + e)], 1);
    } else {
        int node = ((blockIdx.x - WPREP_BLKS - EDGE_BLKS) * blockDim.x + threadIdx.x) >> 5;
        if (node >= N_NODES) return;
        int lane = threadIdx.x & 31;
        int c = __ldg(cncpt + node);
        float4 v = __ldg(reinterpret_cast<const float4*>(emb + (size_t)c * D) + lane);
        __half2 h0 = __floats2half2_rn(v.x, v.y);
        __half2 h1 = __floats2half2_rn(v.z, v.w);
        uint2 w;
        memcpy(&w.x, &h0, 4); memcpy(&w.y, &h1, 4);
        reinterpret_cast<uint2*>(g_x016 + (size_t)node * D)[lane] = w;
    }
}

// ---------------------------------------------------------------------------
// Single-pass scan with decoupled lookback (98 blocks co-resident).
// Zeroes each count after reading it (self-clean for the next call).
// ---------------------------------------------------------------------------
__global__ void scan_kernel() {
    __shared__ int wsum[32];
    __shared__ int s_pref;
    const int t = threadIdx.x, lane = t & 31, wid = t >> 5;
    const int j = blockIdx.x;
    int i = j * SCAN_BS + t;
    int v = (i < N_NODES) ? g_counts[i] : 0;
    if (i < N_NODES) g_counts[i] = 0;   // self-clean
    int s = v;
#pragma unroll
    for (int o = 1; o < 32; o <<= 1) {
        int y = __shfl_up_sync(0xffffffffu, s, o);
        if (lane >= o) s += y;
    }
    if (lane == 31) wsum[wid] = s;
    __syncthreads();
    if (wid == 0) {
        int ws = wsum[lane];
#pragma unroll
        for (int o = 1; o < 32; o <<= 1) {
            int y = __shfl_up_sync(0xffffffffu, ws, o);
            if (lane >= o) ws += y;
        }
        wsum[lane] = ws;
    }
    __syncthreads();
    int incl = s + (wid ? wsum[wid - 1] : 0);
    if (t == SCAN_BS - 1)
        atomicExch(&g_sflag[j], incl + 1);
    if (wid == 0) {
        int p = 0;
        for (int k = lane; k < j; k += 32) {
            int f;
            do { f = atomicAdd(&g_sflag[k], 0); } while (f == 0);
            p += f - 1;
        }
#pragma unroll
        for (int o = 16; o; o >>= 1) p += __shfl_xor_sync(0xffffffffu, p, o);
        if (lane == 0) s_pref = p;
    }
    __syncthreads();
    if (i < N_NODES)
        g_rowptr[i] = s_pref + incl - v;
    if (i == 0) g_rowptr[N_NODES] = N_EDGES;
}

// ---------------------------------------------------------------------------
// fill_csr, ATOMIC-FREE: position = rowptr[dst[e]] + rank[e] (rank captured
// during the histogram). Pure bandwidth: coalesced dst/rank/src reads,
// L2 rowptr gather, scattered 4B store.
// ---------------------------------------------------------------------------
__global__ void fill_csr_kernel(const int* __restrict__ src,
                                const int* __restrict__ dst) {
    int e = blockIdx.x * blockDim.x + threadIdx.x;
    if (e >= N_EDGES) return;
    int d = __ldg(dst + e);
    int p = __ldg(g_rowptr + d) + __ldg(g_rank + e);
    g_csrsrc[p] = __ldg(src + e);
}

// ---------------------------------------------------------------------------
// CSR gather-aggregation over fp16 rows (256 B): warp per node, lane owns
// features 4l..4l+3 (uint2 = 4 halves); shfl-broadcast indices, 4 row loads
// in flight (1 KB/warp). fp32 accumulate; fp16 output.
// ---------------------------------------------------------------------------
template <bool FIRST>
__global__ void __launch_bounds__(256) agg16_kernel() {
    int node = (blockIdx.x * blockDim.x + threadIdx.x) >> 5;
    if (node >= N_NODES) return;
    int lane = threadIdx.x & 31;
    const __half* __restrict__ xin = FIRST ? g_x016 : g_h16;
    int beg = __ldg(g_rowptr + node);
    int end = __ldg(g_rowptr + node + 1);

    float4 a0 = make_float4(0.f, 0.f, 0.f, 0.f);
    float4 a1 = make_float4(0.f, 0.f, 0.f, 0.f);
    int e = beg;
    while (e < end) {
        int n = end - e; if (n > 32) n = 32;
        int idx = (lane < n) ? __ldg(g_csrsrc + e + lane) : 0;
        int j = 0;
        for (; j + 4 <= n; j += 4) {
            int s0 = __shfl_sync(0xffffffffu, idx, j);
            int s1 = __shfl_sync(0xffffffffu, idx, j + 1);
            int s2 = __shfl_sync(0xffffffffu, idx, j + 2);
            int s3 = __shfl_sync(0xffffffffu, idx, j + 3);
            uint2 r0 = __ldg(reinterpret_cast<const uint2*>(xin + (size_t)s0 * D) + lane);
            uint2 r1 = __ldg(reinterpret_cast<const uint2*>(xin + (size_t)s1 * D) + lane);
            uint2 r2 = __ldg(reinterpret_cast<const uint2*>(xin + (size_t)s2 * D) + lane);
            uint2 r3 = __ldg(reinterpret_cast<const uint2*>(xin + (size_t)s3 * D) + lane);
            float2 f;
            f = __half22float2(*reinterpret_cast<__half2*>(&r0.x)); a0.x += f.x; a0.y += f.y;
            f = __half22float2(*reinterpret_cast<__half2*>(&r0.y)); a0.z += f.x; a0.w += f.y;
            f = __half22float2(*reinterpret_cast<__half2*>(&r1.x)); a1.x += f.x; a1.y += f.y;
            f = __half22float2(*reinterpret_cast<__half2*>(&r1.y)); a1.z += f.x; a1.w += f.y;
            f = __half22float2(*reinterpret_cast<__half2*>(&r2.x)); a0.x += f.x; a0.y += f.y;
            f = __half22float2(*reinterpret_cast<__half2*>(&r2.y)); a0.z += f.x; a0.w += f.y;
            f = __half22float2(*reinterpret_cast<__half2*>(&r3.x)); a1.x += f.x; a1.y += f.y;
            f = __half22float2(*reinterpret_cast<__half2*>(&r3.y)); a1.z += f.x; a1.w += f.y;
        }
        for (; j < n; j++) {
            int s0 = __shfl_sync(0xffffffffu, idx, j);
            uint2 r0 = __ldg(reinterpret_cast<const uint2*>(xin + (size_t)s0 * D) + lane);
            float2 f;
            f = __half22float2(*reinterpret_cast<__half2*>(&r0.x)); a0.x += f.x; a0.y += f.y;
            f = __half22float2(*reinterpret_cast<__half2*>(&r0.y)); a0.z += f.x; a0.w += f.y;
        }
        e += n;
    }
    a0.x += a1.x; a0.y += a1.y; a0.z += a1.z; a0.w += a1.w;
    __half2 h0 = __floats2half2_rn(a0.x, a0.y);
    __half2 h1 = __floats2half2_rn(a0.z, a0.w);
    uint2 w;
    memcpy(&w.x, &h0, 4); memcpy(&w.y, &h1, 4);
    reinterpret_cast<uint2*>(g_agg16 + (size_t)node * D)[lane] = w;
}

// ---------------------------------------------------------------------------
// fp16 mma.sync helper (sm_80+ PTX; fp32 accumulate)
// ---------------------------------------------------------------------------
__device__ __forceinline__ void mma16816(float* c, const uint32_t* a,
                                         const uint32_t* b) {
    asm volatile(
        "mma.sync.aligned.m16n8k16.row.col.f32.f16.f16.f32 "
        "{%0,%1,%2,%3}, {%4,%5,%6,%7}, {%8,%9}, {%0,%1,%2,%3};"
        : "+f"(c[0]), "+f"(c[1]), "+f"(c[2]), "+f"(c[3])
        : "r"(a[0]), "r"(a[1]), "r"(a[2]), "r"(a[3]), "r"(b[0]), "r"(b[1]));
}

// ---------------------------------------------------------------------------
// Tensor-core MLP, single-pass fp16 (R14 verified). CTA = 128 nodes x 128
// features, 256 threads, warps 4x2 (32x64 tiles), smem 69632 B -> 2 CTAs/SM.
//   FINAL=false: writes y=relu(agg@W^T+b) to g_h16 (fp16).
//   FINAL=true : fuses out = sigmoid(y . wout + bout).
// ---------------------------------------------------------------------------
template <bool FINAL>
__global__ void __launch_bounds__(256) mlp_mma_kernel(const float* __restrict__ b,
                                                      const float* __restrict__ wout,
                                                      const float* __restrict__ bout,
                                                      float* __restrict__ out) {
    extern __shared__ uint32_t shw[];
    uint32_t* Xs = shw;                // [128][68]
    uint32_t* Ws = shw + 8704;         // [128][68]
    __shared__ float sb[128];
    __shared__ float swout[128];
    __shared__ float nodeSum[128];

    const int t = threadIdx.x;
    const int wid = t >> 5, lane = t & 31;
    const int gbase = blockIdx.x * 128;

    // Stage W (straight copy of packed fp16 weights; L2-resident 32 KB)
    {
        const uint32_t* srcW = g_Wpk16 + (FINAL ? 8192 : 0);
#pragma unroll
        for (int i = 0; i < 32; i++) {
            int idx = t + 256 * i;            // 8192 total
            int f = idx >> 6, p = idx & 63;
            Ws[f * 68 + p] = __ldg(srcW + idx);
        }
    }
    // Stage X: raw uint4 copy of fp16 agg rows (16 uint4 per 256-B row)
#pragma unroll
    for (int i = 0; i < 8; i++) {
        int idx = t + 256 * i;                // 2048 total
        int r = idx >> 4, q = idx & 15;
        int node = gbase + r;
        uint4 v = make_uint4(0u, 0u, 0u, 0u);
        if (node < N_NODES)
            v = *(reinterpret_cast<const uint4*>(g_agg16 + (size_t)node * D) + q);
        *reinterpret_cast<uint4*>(Xs + r * 68 + 4 * q) = v;
    }
    if (t < 128) {
        sb[t] = __ldg(b + t);
        if (FINAL) { swout[t] = __ldg(wout + t); nodeSum[t] = 0.f; }
    }
    __syncthreads();

    const int m0 = (wid >> 1) * 32, n0 = (wid & 1) * 64;
    float acc[2][8][4];
#pragma unroll
    for (int mt = 0; mt < 2; mt++)
#pragma unroll
        for (int nt = 0; nt < 8; nt++)
#pragma unroll
            for (int j = 0; j < 4; j++) acc[mt][nt][j] = 0.f;

    const int lq = lane >> 2, lr = lane & 3;
#pragma unroll
    for (int ks = 0; ks < 8; ks++) {
        const int kp = ks * 8 + lr;
        uint32_t a[2][4];
#pragma unroll
        for (int mt = 0; mt < 2; mt++) {
            int r0i = m0 + mt * 16 + lq;
            a[mt][0] = Xs[r0i * 68 + kp];
            a[mt][1] = Xs[(r0i + 8) * 68 + kp];
            a[mt][2] = Xs[r0i * 68 + kp + 4];
            a[mt][3] = Xs[(r0i + 8) * 68 + kp + 4];
        }
        uint32_t bf[8][2];
#pragma unroll
        for (int nt = 0; nt < 8; nt++) {
            int nr = n0 + nt * 8 + lq;
            bf[nt][0] = Ws[nr * 68 + kp];
            bf[nt][1] = Ws[nr * 68 + kp + 4];
        }
#pragma unroll
        for (int mt = 0; mt < 2; mt++)
#pragma unroll
            for (int nt = 0; nt < 8; nt++)
                mma16816(acc[mt][nt], a[mt], bf[nt]);
    }

    if (!FINAL) {
#pragma unroll
        for (int mt = 0; mt < 2; mt++) {
            int rA = m0 + mt * 16 + lq;
            int nodeA = gbase + rA, nodeB = nodeA + 8;
#pragma unroll
            for (int nt = 0; nt < 8; nt++) {
                int c = n0 + nt * 8 + lr * 2;
                if (nodeA < N_NODES) {
                    __half2 y = __floats2half2_rn(
                        fmaxf(acc[mt][nt][0] + sb[c],     0.f),
                        fmaxf(acc[mt][nt][1] + sb[c + 1], 0.f));
                    *reinterpret_cast<__half2*>(g_h16 + (size_t)nodeA * D + c) = y;
                }
                if (nodeB < N_NODES) {
                    __half2 y = __floats2half2_rn(
                        fmaxf(acc[mt][nt][2] + sb[c],     0.f),
                        fmaxf(acc[mt][nt][3] + sb[c + 1], 0.f));
                    *reinterpret_cast<__half2*>(g_h16 + (size_t)nodeB * D + c) = y;
                }
            }
        }
    } else {
#pragma unroll
        for (int mt = 0; mt < 2; mt++) {
            float pA = 0.f, pB = 0.f;
            int rA = m0 + mt * 16 + lq;
#pragma unroll
            for (int nt = 0; nt < 8; nt++) {
                int c = n0 + nt * 8 + lr * 2;
                pA += fmaxf(acc[mt][nt][0] + sb[c],     0.f) * swout[c]
                    + fmaxf(acc[mt][nt][1] + sb[c + 1], 0.f) * swout[c + 1];
                pB += fmaxf(acc[mt][nt][2] + sb[c],     0.f) * swout[c]
                    + fmaxf(acc[mt][nt][3] + sb[c + 1], 0.f) * swout[c + 1];
            }
            pA += __shfl_xor_sync(0xffffffffu, pA, 1);
            pA += __shfl_xor_sync(0xffffffffu, pA, 2);
            pB += __shfl_xor_sync(0xffffffffu, pB, 1);
            pB += __shfl_xor_sync(0xffffffffu, pB, 2);
            if (lr == 0) {
                atomicAdd(&nodeSum[rA], pA);
                atomicAdd(&nodeSum[rA + 8], pB);
            }
        }
        __syncthreads();
        if (t < 128) {
            int node = gbase + t;
            if (node < N_NODES)
                out[node] = 1.f / (1.f + expf(-(nodeSum[t] + __ldg(bout))));
        }
    }
}

// ---------------------------------------------------------------------------
extern "C" void kernel_launch(void* const* d_in, const int* in_sizes, int n_in,
                              void* d_out, int out_size) {
    const int*   cncpt = (const int*)d_in[0];
    const int*   src   = (const int*)d_in[1];
    const int*   dst   = (const int*)d_in[2];
    const float* emb   = (const float*)d_in[3];
    const float* W1    = (const float*)d_in[4];
    const float* b1    = (const float*)d_in[5];
    const float* W2    = (const float*)d_in[6];
    const float* b2    = (const float*)d_in[7];
    const float* Wout  = (const float*)d_in[8];
    const float* bout  = (const float*)d_in[9];
    float* out = (float*)d_out;

    const int MLP_SMEM = 2 * 8704 * 4;   // 69632 B -> 2 CTAs/SM
    cudaFuncSetAttribute(mlp_mma_kernel<false>, cudaFuncAttributeMaxDynamicSharedMemorySize, MLP_SMEM);
    cudaFuncSetAttribute(mlp_mma_kernel<true>,  cudaFuncAttributeMaxDynamicSharedMemorySize, MLP_SMEM);

    const int MLP_BLKS = (N_NODES + 127) / 128;   // 782

    // 1: W convert + histogram(rank capture) + x0 gather, one launch
    prep_hist_gather_kernel<<<WPREP_BLKS + EDGE_BLKS + WARP_BLKS, 256>>>(
        W1, W2, dst, cncpt, emb);
    // 2: scan (self-cleaning counts)
    scan_kernel<<<SCAN_NB, SCAN_BS>>>();
    // 3: atomic-free CSR fill
    fill_csr_kernel<<<EDGE_BLKS, 256>>>(src, dst);

    // Layer 1
    agg16_kernel<true><<<WARP_BLKS, 256>>>();
    mlp_mma_kernel<false><<<MLP_BLKS, 256, MLP_SMEM>>>(b1, nullptr, nullptr, nullptr);

    // Layer 2 (+ fused sigmoid head)
    agg16_kernel<false><<<WARP_BLKS, 256>>>();
    mlp_mma_kernel<true><<<MLP_BLKS, 256, MLP_SMEM>>>(b2, Wout, bout, out);

    (void)in_sizes; (void)n_in; (void)out_size;
}